// round 9
// baseline (speedup 1.0000x reference)
#include <cuda_runtime.h>

// SubGraphAvgPool: out[b,g,d] = mean(h[b,g,d], h[b,4g+1..4g+4,d]),  B=16, N=8193, D=512, G=2048.
//
// 256-thread CTAs, one CTA per g-PAIR (g0=2gi, g1=2gi+1): threads 0..127 handle
// g0's float4 columns, threads 128..255 handle g1's. Per-thread work identical
// to the R6 winner (5 loads, children first), but the CTA's child loads form a
// single contiguous 16KB burst (rows 8gi+1..8gi+8), issued together on one SM.
// regs ~30, 8 CTAs/SM -> full 64 warps/SM.
//
// Cache hints (unchanged):
//   - child rows >= 2049 (g >= 512): __ldcs  (single-use stream)
//   - child rows 1..2048:            default (re-read later as g-rows)
//   - g-node row:                    __ldcs  (last use)
//   - output:                        __stcs  (never re-read)

static constexpr int B = 16;
static constexpr long long N = 8193;
static constexpr int D = 512;
static constexpr int G = 2048;
static constexpr int DV = D / 4;   // 128 float4 per row
static constexpr int GP = G / 2;   // 1024 g-pairs per batch

__global__ __launch_bounds__(256, 8)
void subgraph_avgpool_kernel(const float* __restrict__ h, float* __restrict__ out) {
    const int blk  = blockIdx.x;        // 0 .. B*GP-1
    const int gi   = blk & (GP - 1);    // GP = 1024 = 2^10
    const int b    = blk >> 10;
    const int half = threadIdx.x >> 7;  // 0 or 1
    const int dv   = threadIdx.x & 127; // 0 .. 127

    const int g = 2 * gi + half;

    const float4* __restrict__ hp =
        reinterpret_cast<const float4*>(h) + (long long)b * (N * DV) + dv;

    // Child rows 4g+1..4g+4 first: CTA-wide this is rows 8gi+1..8gi+8,
    // one contiguous 16KB DRAM burst.
    const float4* p = hp + (long long)(4 * g + 1) * DV;
    float4 a1, a2, a3, a4;
    if (g >= 512) {
        a1 = __ldcs(p);          a2 = __ldcs(p + DV);
        a3 = __ldcs(p + 2 * DV); a4 = __ldcs(p + 3 * DV);
    } else {
        a1 = __ldg(p);           a2 = __ldg(p + DV);
        a3 = __ldg(p + 2 * DV);  a4 = __ldg(p + 3 * DV);
    }

    // g-node row last: usually an L2 hit, cheap to hide.
    const float4 a0 = __ldcs(hp + (long long)g * DV);

    float4 s;
    s.x = (a0.x + a1.x + a2.x + a3.x + a4.x) * 0.2f;
    s.y = (a0.y + a1.y + a2.y + a3.y + a4.y) * 0.2f;
    s.z = (a0.z + a1.z + a2.z + a3.z + a4.z) * 0.2f;
    s.w = (a0.w + a1.w + a2.w + a3.w + a4.w) * 0.2f;

    __stcs(reinterpret_cast<float4*>(out) + ((long long)b * G + g) * DV + dv, s);
}

extern "C" void kernel_launch(void* const* d_in, const int* in_sizes, int n_in,
                              void* d_out, int out_size) {
    const float* h = (const float*)d_in[0];
    float* out = (float*)d_out;
    subgraph_avgpool_kernel<<<B * GP, 256>>>(h, out);
}

// round 13
// speedup vs baseline: 1.0078x; 1.0078x over previous
#include <cuda_runtime.h>

// SubGraphAvgPool: out[b,g,d] = mean(h[b,g,d], h[b,4g+1..4g+4,d]),  B=16, N=8193, D=512, G=2048.
//
// R6 winner (one CTA per (b,g), 128 threads, one float4/thread, children-first
// load order, streaming hints) with a minimized address-generation prologue:
//   - 2D grid (G, B): no mask/shift to decompose blockIdx
//   - 32-bit unsigned element offsets (max offset < 2^31 bytes)
//
// Cache hints:
//   - child rows >= 2049 (g >= 512): __ldcs  (single-use stream)
//   - child rows 1..2048:            default (re-read later as g-rows)
//   - g-node row:                    __ldcs  (last use)
//   - output:                        __stcs  (never re-read)

static constexpr int B = 16;
static constexpr unsigned N = 8193;
static constexpr int D = 512;
static constexpr unsigned G = 2048;
static constexpr unsigned DV = D / 4;  // 128 float4 per row

__global__ __launch_bounds__(128, 8)
void subgraph_avgpool_kernel(const float* __restrict__ h, float* __restrict__ out) {
    const unsigned g  = blockIdx.x;       // 0 .. 2047
    const unsigned b  = blockIdx.y;       // 0 .. 15
    const unsigned dv = threadIdx.x;      // 0 .. 127

    // All element offsets fit in 32 bits (max ~67M elements = 268MB bytes).
    const float4* __restrict__ hp =
        reinterpret_cast<const float4*>(h) + b * (N * DV) + dv;

    // Child rows 4g+1..4g+4 first: the DRAM-bound contiguous burst.
    const float4* p = hp + (4u * g + 1u) * DV;
    float4 a1, a2, a3, a4;
    if (g >= 512u) {
        a1 = __ldcs(p);           a2 = __ldcs(p + DV);
        a3 = __ldcs(p + 2u * DV); a4 = __ldcs(p + 3u * DV);
    } else {
        a1 = __ldg(p);            a2 = __ldg(p + DV);
        a3 = __ldg(p + 2u * DV);  a4 = __ldg(p + 3u * DV);
    }

    // g-node row last: usually an L2 hit, cheap to hide.
    const float4 a0 = __ldcs(hp + g * DV);

    float4 s;
    s.x = (a0.x + a1.x + a2.x + a3.x + a4.x) * 0.2f;
    s.y = (a0.y + a1.y + a2.y + a3.y + a4.y) * 0.2f;
    s.z = (a0.z + a1.z + a2.z + a3.z + a4.z) * 0.2f;
    s.w = (a0.w + a1.w + a2.w + a3.w + a4.w) * 0.2f;

    __stcs(reinterpret_cast<float4*>(out) + (b * G + g) * DV + dv, s);
}

extern "C" void kernel_launch(void* const* d_in, const int* in_sizes, int n_in,
                              void* d_out, int out_size) {
    const float* h = (const float*)d_in[0];
    float* out = (float*)d_out;
    dim3 grid(G, B);
    subgraph_avgpool_kernel<<<grid, 128>>>(h, out);
}